// round 1
// baseline (speedup 1.0000x reference)
#include <cuda_runtime.h>

// SphericalExpansion: per-edge radial×angular outer product scattered into
// out[idx_i, z[idx_j], n, m]  (20000, 4, 8, 16) fp32.
//
// Strategy: warp per edge (grid-stride). lane = n*4 + m_quad; each lane owns a
// contiguous float4 of the 128-float destination segment, committed with a
// single red.global.add.v4.f32 (4x fewer atomic ops than scalar atomicAdd).

#define PI_F 3.14159265358979f

__device__ __forceinline__ void red_add_v4(float* p, float a, float b, float c, float d) {
    asm volatile("red.global.add.v4.f32 [%0], {%1,%2,%3,%4};"
                 :: "l"(p), "f"(a), "f"(b), "f"(c), "f"(d) : "memory");
}

__global__ __launch_bounds__(256)
void sph_expand_kernel(
    const float* __restrict__ dist,
    const float* __restrict__ dirs,
    const float* __restrict__ W,      // (4, 8, 16) row-major
    const int*   __restrict__ zarr,   // (N_ATOMS)
    const int*   __restrict__ idx_i,
    const int*   __restrict__ idx_j,
    float*       __restrict__ out,    // (N_ATOMS, 4, 8, 16)
    int n_edges)
{
    const int lane = threadIdx.x & 31;
    const int gw   = (blockIdx.x * blockDim.x + threadIdx.x) >> 5;
    const int nw   = (gridDim.x * blockDim.x) >> 5;

    // lane -> (n, m_quad). m values are m_base..m_base+3, m_base = mq*4.
    // l(m) table: {0,1,1,1, 2,2,2,2, 2,3,3,3, 3,3,3,3}
    // Within a quad at most two distinct l: lA = l(m_base), lB = l(m_base+1..3).
    const int n  = lane >> 2;
    const int mq = lane & 3;
    const int lA = (mq == 0) ? 0 : (mq == 3 ? 3 : 2);
    const int lB = (mq == 0) ? 1 : (mq == 1 ? 2 : 3);

    // Hoist W rows into registers: loop-invariant per lane.
    float wA[16], wB[16];
    #pragma unroll
    for (int k = 0; k < 16; ++k) {
        wA[k] = W[(lA * 8 + n) * 16 + k];
        wB[k] = W[(lB * 8 + n) * 16 + k];
    }

    // Gaussian center for this lane's k (= lane & 15): linspace(0, 5, 16).
    const float ck = (float)(lane & 15) * (5.0f / 15.0f);

    for (int e = gw; e < n_edges; e += nw) {
        const float d  = dist[e];
        const float x  = dirs[3 * e + 0];
        const float y  = dirs[3 * e + 1];
        const float zc = dirs[3 * e + 2];
        const int   ii = idx_i[e];
        const int   jj = idx_j[e];
        const int   zj = zarr[jj];

        // shifted cosine cutoff: t clamped to [0,1] handles all three branches
        float t  = fminf(fmaxf((d - 4.5f) * 2.0f, 0.0f), 1.0f);
        float fc = 0.5f * (__cosf(t * PI_F) + 1.0f);

        // Gaussian basis value for k = lane & 15 (lanes 16..31 duplicate 0..15)
        float dk = d - ck;
        float g  = __expf(-2.0f * dk * dk);   // sigma = 0.5 -> 1/(2s^2) = 2

        // Radial contractions for the two l values this lane needs.
        float accA = 0.f, accB = 0.f;
        #pragma unroll
        for (int k = 0; k < 16; ++k) {
            float gk = __shfl_sync(0xffffffffu, g, k);
            accA = fmaf(gk, wA[k], accA);
            accB = fmaf(gk, wB[k], accB);
        }
        accA *= fc;
        accB *= fc;

        // Real spherical harmonics l<=3 (all 16, shared subexpressions).
        const float x2 = x * x, y2 = y * y, z2 = zc * zc;
        const float Y0  = 0.28209479177387814f;
        const float Y1  = 0.4886025119029199f * y;
        const float Y2  = 0.4886025119029199f * zc;
        const float Y3  = 0.4886025119029199f * x;
        const float Y4  = 1.0925484305920792f * x * y;
        const float Y5  = 1.0925484305920792f * y * zc;
        const float Y6  = 0.31539156525252005f * (3.0f * z2 - 1.0f);
        const float Y7  = 1.0925484305920792f * x * zc;
        const float Y8  = 0.5462742152960396f * (x2 - y2);
        const float Y9  = 0.5900435899266435f * y * (3.0f * x2 - y2);
        const float Y10 = 2.890611442640554f  * x * y * zc;
        const float Y11 = 0.4570457994644658f * y * (5.0f * z2 - 1.0f);
        const float Y12 = 0.3731763325901154f * zc * (5.0f * z2 - 3.0f);
        const float Y13 = 0.4570457994644658f * x * (5.0f * z2 - 1.0f);
        const float Y14 = 1.445305721320277f  * zc * (x2 - y2);
        const float Y15 = 0.5900435899266435f * x * (x2 - 3.0f * y2);

        // Select this lane's quad of Y values (predicated selects, no memory).
        float s0, s1, s2, s3;
        if (mq == 0)      { s0 = Y0;  s1 = Y1;  s2 = Y2;  s3 = Y3;  }
        else if (mq == 1) { s0 = Y4;  s1 = Y5;  s2 = Y6;  s3 = Y7;  }
        else if (mq == 2) { s0 = Y8;  s1 = Y9;  s2 = Y10; s3 = Y11; }
        else              { s0 = Y12; s1 = Y13; s2 = Y14; s3 = Y15; }

        // m_base element uses l(m_base)=lA; the other three use lB.
        const float vx = accA * s0;
        const float vy = accB * s1;
        const float vz = accB * s2;
        const float vw = accB * s3;

        // out offset: ((ii*4 + zj)*8 + n)*16 + mq*4  ==  rid*128 + lane*4
        const size_t base = ((size_t)ii * 4 + (size_t)zj) * 128 + (size_t)lane * 4;
        red_add_v4(out + base, vx, vy, vz, vw);
    }
}

extern "C" void kernel_launch(void* const* d_in, const int* in_sizes, int n_in,
                              void* d_out, int out_size) {
    const float* dist = (const float*)d_in[0];
    const float* dirs = (const float*)d_in[1];
    const float* W    = (const float*)d_in[2];
    // d_in[3] = centers: recomputed analytically (linspace(0, RC, 16))
    const int* z      = (const int*)d_in[4];
    const int* idx_i  = (const int*)d_in[5];
    const int* idx_j  = (const int*)d_in[6];
    const int n_edges = in_sizes[0];

    // d_out is poisoned; the scatter is accumulate-only, so zero it first.
    cudaMemsetAsync(d_out, 0, (size_t)out_size * sizeof(float), 0);

    const int block = 256;                 // 8 warps
    const int grid  = 148 * 16;            // persistent-ish grid-stride, ~42 edges/warp
    sph_expand_kernel<<<grid, block>>>(dist, dirs, W, z, idx_i, idx_j,
                                       (float*)d_out, n_edges);
}